// round 9
// baseline (speedup 1.0000x reference)
#include <cuda_runtime.h>
#include <cuda_bf16.h>
#include <math.h>

// ---------------------------------------------------------------------------
// Problem constants
// ---------------------------------------------------------------------------
#define M_TOK 22016   // N*T = 512*43
#define NB    512
#define TT    43
#define HH    128
#define DKH   96
#define DFF_  2048
#define OUTV  8000
#define OUTP  8064    // padded to multiple of 128
#define QKVW  576     // 6*96 packed
#define QKVP  640     // padded

// ---------------------------------------------------------------------------
// Device-global scratch (no allocation allowed)
// ---------------------------------------------------------------------------
__device__ float d_x0  [M_TOK * HH];      // embed, exact fp32
__device__ float d_x0r [M_TOK * HH];      // embed, tf32-rounded
__device__ float d_qkvb[M_TOK * QKVW];    // packed q1 k1 v1 q2 k2 v2
__device__ float d_heads[M_TOK * 192];    // concat(h1,h2), tf32-rounded
__device__ float d_mhb [M_TOK * HH];      // proj output
__device__ float d_x1  [M_TOK * HH];      // LN1 out exact
__device__ float d_x1r [M_TOK * HH];      // LN1 out rounded
__device__ float d_ff  [M_TOK * DFF_];    // relu(ff1), rounded
__device__ float d_ffo [M_TOK * HH];      // ff2 output
__device__ float d_x2r [M_TOK * HH];      // LN2 out rounded

__device__ float w_qkv [QKVP * HH];       // packed+padded, rounded
__device__ float b_qkvp[QKVP];
__device__ float w_proj[HH * 192];
__device__ float w_ff1 [DFF_ * HH];
__device__ float w_ff2 [HH * DFF_];
__device__ float w_fin [OUTP * HH];       // padded rows zeroed
__device__ float b_finp[OUTP];

// ---------------------------------------------------------------------------
// Helpers
// ---------------------------------------------------------------------------
__device__ __forceinline__ float rna_tf32(float x) {
    unsigned int u;
    asm("cvt.rna.tf32.f32 %0, %1;" : "=r"(u) : "f"(x));
    return __uint_as_float(u);
}
__device__ __forceinline__ unsigned int smem_u32(const void* p) {
    return (unsigned int)__cvta_generic_to_shared(p);
}
__device__ __forceinline__ void cp16(unsigned int dst, const float* src) {
    asm volatile("cp.async.cg.shared.global [%0], [%1], 16;\n" :: "r"(dst), "l"(src));
}
__device__ __forceinline__ void mma_tf32(float (&d)[4], const unsigned int (&a)[4],
                                         const unsigned int (&b)[2]) {
    asm volatile(
        "mma.sync.aligned.m16n8k8.row.col.f32.tf32.tf32.f32 "
        "{%0,%1,%2,%3},{%4,%5,%6,%7},{%8,%9},{%0,%1,%2,%3};"
        : "+f"(d[0]), "+f"(d[1]), "+f"(d[2]), "+f"(d[3])
        : "r"(a[0]), "r"(a[1]), "r"(a[2]), "r"(a[3]), "r"(b[0]), "r"(b[1]));
}

// ---------------------------------------------------------------------------
// GEMM: C[M,N] = A[M,K] @ B[N,K]^T + bias.  A,B fp32 buffers holding
// tf32-pre-rounded values. BN=128, BK=32, 256 threads = 8 warps (2M x 4N).
// smem pad 36 => all fragment LDS conflict-free. 2-stage cp.async pipeline.
// B rows must cover n0..n0+127 (callers pad weights); stores masked n<Nstore.
// ---------------------------------------------------------------------------
template <int BM, bool RELU, bool ROUND>
__global__ void __launch_bounds__(256, 1)
gemm_tn(const float* __restrict__ A, const float* __restrict__ B,
        const float* __restrict__ bias, float* __restrict__ C,
        int K, int ldc, int Nstore)
{
    constexpr int WM = BM / 2;        // warp M-tile
    constexpr int MF = WM / 16;       // m-frags per warp
    constexpr int SS = BM * 36 + 128 * 36;   // floats per stage
    extern __shared__ float sm[];

    const int tid    = threadIdx.x;
    const int warpId = tid >> 5;
    const int lane   = tid & 31;
    const int m0     = blockIdx.x * BM;
    const int n0     = blockIdx.y * 128;
    const int KT     = K >> 5;

    const float* Ab = A + (size_t)m0 * K;
    const float* Bb = B + (size_t)n0 * K;

    float acc[MF][4][4];
#pragma unroll
    for (int i = 0; i < MF; i++)
#pragma unroll
        for (int j = 0; j < 4; j++)
#pragma unroll
            for (int q = 0; q < 4; q++) acc[i][j][q] = 0.f;

    auto load_stage = [&](int buf, int kt) {
        float* As = sm + buf * SS;
        float* Bs = As + BM * 36;
#pragma unroll
        for (int i = 0; i < BM / 32; i++) {
            int idx = tid + 256 * i;
            int row = idx >> 3, c = idx & 7;
            cp16(smem_u32(As + row * 36 + c * 4),
                 Ab + (size_t)row * K + kt * 32 + c * 4);
        }
#pragma unroll
        for (int i = 0; i < 4; i++) {
            int idx = tid + 256 * i;
            int row = idx >> 3, c = idx & 7;
            cp16(smem_u32(Bs + row * 36 + c * 4),
                 Bb + (size_t)row * K + kt * 32 + c * 4);
        }
    };

    const int wr = warpId >> 2;   // 0..1
    const int wc = warpId & 3;    // 0..3
    const int g  = lane >> 2;     // 0..7
    const int tg = lane & 3;      // 0..3

    load_stage(0, 0);
    asm volatile("cp.async.commit_group;\n" ::);
    int buf = 0;
    for (int kt = 0; kt < KT; ++kt) {
        asm volatile("cp.async.wait_group 0;\n" ::);
        __syncthreads();
        if (kt + 1 < KT) {
            load_stage(buf ^ 1, kt + 1);
            asm volatile("cp.async.commit_group;\n" ::);
        }
        const float* As = sm + buf * SS;
        const float* Bs = As + BM * 36;
        const float* Aw = As + (wr * WM + g) * 36 + tg;
        const float* Bw = Bs + (wc * 32 + g) * 36 + tg;
#pragma unroll
        for (int ks = 0; ks < 4; ++ks) {
            const int k0 = ks * 8;
            unsigned int a[MF][4], b[4][2];
#pragma unroll
            for (int mf = 0; mf < MF; ++mf) {
                const float* p = Aw + mf * 16 * 36 + k0;
                a[mf][0] = __float_as_uint(p[0]);
                a[mf][1] = __float_as_uint(p[8 * 36]);
                a[mf][2] = __float_as_uint(p[4]);
                a[mf][3] = __float_as_uint(p[8 * 36 + 4]);
            }
#pragma unroll
            for (int nf = 0; nf < 4; ++nf) {
                const float* p = Bw + nf * 8 * 36 + k0;
                b[nf][0] = __float_as_uint(p[0]);
                b[nf][1] = __float_as_uint(p[4]);
            }
#pragma unroll
            for (int mf = 0; mf < MF; ++mf)
#pragma unroll
                for (int nf = 0; nf < 4; ++nf)
                    mma_tf32(acc[mf][nf], a[mf], b[nf]);
        }
        __syncthreads();
        buf ^= 1;
    }

    // Epilogue: c0@(g, tg*2) c1@(g, tg*2+1) c2@(g+8, tg*2) c3@(g+8, tg*2+1)
#pragma unroll
    for (int mf = 0; mf < MF; ++mf) {
#pragma unroll
        for (int nf = 0; nf < 4; ++nf) {
            const int c = n0 + wc * 32 + nf * 8 + tg * 2;
            if (c < Nstore) {
                const float bi0 = bias[c];
                const float bi1 = bias[c + 1];
#pragma unroll
                for (int h = 0; h < 2; ++h) {
                    const int r = m0 + wr * WM + mf * 16 + g + h * 8;
                    float v0 = acc[mf][nf][h * 2 + 0] + bi0;
                    float v1 = acc[mf][nf][h * 2 + 1] + bi1;
                    if (RELU) { v0 = fmaxf(v0, 0.f); v1 = fmaxf(v1, 0.f); }
                    if (ROUND) { v0 = rna_tf32(v0); v1 = rna_tf32(v1); }
                    float2 val; val.x = v0; val.y = v1;
                    *reinterpret_cast<float2*>(C + (size_t)r * ldc + c) = val;
                }
            }
        }
    }
}

// ---------------------------------------------------------------------------
// Attention: one CTA per (batch, head). All fp32 in smem.
// ---------------------------------------------------------------------------
__global__ void __launch_bounds__(256, 1)
attn_kernel(const float* __restrict__ qkv, float* __restrict__ heads)
{
    extern __shared__ float sm[];
    float* q  = sm;                 // 43*97
    float* k  = q + 43 * 97;
    float* v  = k + 43 * 97;
    float* sc = v + 43 * 97;        // 43*44

    const int n = blockIdx.x, head = blockIdx.y;
    const int tid = threadIdx.x;
    const float* base = qkv + (size_t)(n * TT) * QKVW + head * 288;

    for (int idx = tid; idx < TT * DKH; idx += 256) {
        int i = idx / DKH, d = idx - i * DKH;
        const float* row = base + (size_t)i * QKVW;
        q[i * 97 + d] = row[d];
        k[i * 97 + d] = row[96 + d];
        v[i * 97 + d] = row[192 + d];
    }
    __syncthreads();

    const float scale = 0.10206207261596577f;   // 1/sqrt(96)
    for (int p = tid; p < TT * TT; p += 256) {
        int i = p / TT, j = p - i * TT;
        float s = 0.f;
#pragma unroll 16
        for (int d = 0; d < DKH; ++d) s += q[i * 97 + d] * k[j * 97 + d];
        sc[i * 44 + j] = s * scale;
    }
    __syncthreads();

    const int warpId = tid >> 5, lane = tid & 31;
    for (int i = warpId; i < TT; i += 8) {
        float x0 = (lane < TT)      ? sc[i * 44 + lane]      : -1e30f;
        float x1 = (lane + 32 < TT) ? sc[i * 44 + lane + 32] : -1e30f;
        float m = fmaxf(x0, x1);
#pragma unroll
        for (int o = 16; o; o >>= 1) m = fmaxf(m, __shfl_xor_sync(0xffffffffu, m, o));
        float e0 = (lane < TT)      ? expf(x0 - m) : 0.f;
        float e1 = (lane + 32 < TT) ? expf(x1 - m) : 0.f;
        float s = e0 + e1;
#pragma unroll
        for (int o = 16; o; o >>= 1) s += __shfl_xor_sync(0xffffffffu, s, o);
        float inv = 1.f / s;
        if (lane < TT)      sc[i * 44 + lane]      = e0 * inv;
        if (lane + 32 < TT) sc[i * 44 + lane + 32] = e1 * inv;
    }
    __syncthreads();

    float* out = heads + (size_t)(n * TT) * 192 + head * 96;
    for (int idx = tid; idx < TT * DKH; idx += 256) {
        int i = idx / DKH, d = idx - i * DKH;
        float o = 0.f;
#pragma unroll
        for (int j = 0; j < TT; ++j) o += sc[i * 44 + j] * v[j * 97 + d];
        out[(size_t)i * 192 + d] = rna_tf32(o);
    }
}

// ---------------------------------------------------------------------------
// Fused add + LayerNorm. One warp per token (H=128 => 4 elems/lane).
// ---------------------------------------------------------------------------
__global__ void __launch_bounds__(256, 1)
add_ln_kernel(const float* __restrict__ a, const float* __restrict__ res,
              const float* __restrict__ gam, const float* __restrict__ bet,
              float* __restrict__ outE, float* __restrict__ outR)
{
    const int warpId = threadIdx.x >> 5, lane = threadIdx.x & 31;
    const int m = blockIdx.x * 8 + warpId;
    const float* ap = a   + (size_t)m * HH;
    const float* rp = res + (size_t)m * HH;
    float x[4];
    float s = 0.f, ss = 0.f;
#pragma unroll
    for (int q = 0; q < 4; q++) {
        x[q] = ap[lane + 32 * q] + rp[lane + 32 * q];
        s += x[q]; ss += x[q] * x[q];
    }
#pragma unroll
    for (int o = 16; o; o >>= 1) {
        s  += __shfl_xor_sync(0xffffffffu, s,  o);
        ss += __shfl_xor_sync(0xffffffffu, ss, o);
    }
    const float mean = s * (1.f / 128.f);
    const float var  = ss * (1.f / 128.f) - mean * mean;
    const float rstd = rsqrtf(var + 1e-5f);
#pragma unroll
    for (int q = 0; q < 4; q++) {
        const int h = lane + 32 * q;
        const float y = (x[q] - mean) * rstd * gam[h] + bet[h];
        if (outE) outE[(size_t)m * HH + h] = y;
        outR[(size_t)m * HH + h] = rna_tf32(y);
    }
}

// ---------------------------------------------------------------------------
// Embedding: word + positional, exact + rounded copies.
// ---------------------------------------------------------------------------
__global__ void embed_kernel(const int* __restrict__ inp,
                             const float* __restrict__ emb,
                             const float* __restrict__ pos)
{
    const int idx = blockIdx.x * 256 + threadIdx.x;     // < M_TOK*128
    const int m = idx >> 7, h = idx & 127;
    const int t = m % TT;
    const int id = inp[m];
    const float v = emb[(size_t)id * HH + h] + pos[t * HH + h];
    d_x0[idx]  = v;
    d_x0r[idx] = rna_tf32(v);
}

// ---------------------------------------------------------------------------
// Weight prep kernels (run every call; cheap, graph-capturable)
// ---------------------------------------------------------------------------
__global__ void round_copy_kernel(float* dst, const float* __restrict__ src, int n)
{
    const int i = blockIdx.x * 256 + threadIdx.x;
    if (i < n) dst[i] = rna_tf32(src[i]);
}

__global__ void pack_qkv_w_kernel(const float* __restrict__ Wq1, const float* __restrict__ Wk1,
                                  const float* __restrict__ Wv1, const float* __restrict__ Wq2,
                                  const float* __restrict__ Wk2, const float* __restrict__ Wv2)
{
    const int idx = blockIdx.x * 256 + threadIdx.x;
    if (idx >= QKVP * HH) return;
    const int r = idx >> 7, c = idx & 127;
    float v = 0.f;
    if (r < QKVW) {
        const int sel = r / 96, rr = r - sel * 96;
        const float* W = sel == 0 ? Wq1 : sel == 1 ? Wk1 : sel == 2 ? Wv1
                       : sel == 3 ? Wq2 : sel == 4 ? Wk2 : Wv2;
        v = rna_tf32(W[rr * HH + c]);
    }
    w_qkv[idx] = v;
}

__global__ void pack_qkv_b_kernel(const float* __restrict__ bq1, const float* __restrict__ bk1,
                                  const float* __restrict__ bv1, const float* __restrict__ bq2,
                                  const float* __restrict__ bk2, const float* __restrict__ bv2)
{
    const int i = blockIdx.x * 256 + threadIdx.x;
    if (i >= QKVP) return;
    float v = 0.f;
    if (i < QKVW) {
        const int sel = i / 96, rr = i - sel * 96;
        const float* b = sel == 0 ? bq1 : sel == 1 ? bk1 : sel == 2 ? bv1
                       : sel == 3 ? bq2 : sel == 4 ? bk2 : bv2;
        v = b[rr];
    }
    b_qkvp[i] = v;
}

__global__ void pack_fin_kernel(const float* __restrict__ W, const float* __restrict__ b)
{
    const int idx = blockIdx.x * 256 + threadIdx.x;
    if (idx < OUTP * HH) {
        const int r = idx >> 7;
        w_fin[idx] = (r < OUTV) ? rna_tf32(W[idx]) : 0.f;
    }
    if (idx < OUTP) b_finp[idx] = (idx < OUTV) ? b[idx] : 0.f;
}

// ---------------------------------------------------------------------------
// Launch
// ---------------------------------------------------------------------------
extern "C" void kernel_launch(void* const* d_in, const int* in_sizes, int n_in,
                              void* d_out, int out_size)
{
    const int*   inp   = (const int*)  d_in[0];
    const float* emb   = (const float*)d_in[1];
    const float* pos   = (const float*)d_in[2];
    const float* Wk1   = (const float*)d_in[3];
    const float* bk1   = (const float*)d_in[4];
    const float* Wv1   = (const float*)d_in[5];
    const float* bv1   = (const float*)d_in[6];
    const float* Wq1   = (const float*)d_in[7];
    const float* bq1   = (const float*)d_in[8];
    const float* Wk2   = (const float*)d_in[9];
    const float* bk2   = (const float*)d_in[10];
    const float* Wv2   = (const float*)d_in[11];
    const float* bv2   = (const float*)d_in[12];
    const float* Wq2   = (const float*)d_in[13];
    const float* bq2   = (const float*)d_in[14];
    const float* Wproj = (const float*)d_in[15];
    const float* bproj = (const float*)d_in[16];
    const float* gmh   = (const float*)d_in[17];
    const float* bmh   = (const float*)d_in[18];
    const float* Wff1  = (const float*)d_in[19];
    const float* bff1  = (const float*)d_in[20];
    const float* Wff2  = (const float*)d_in[21];
    const float* bff2  = (const float*)d_in[22];
    const float* gff   = (const float*)d_in[23];
    const float* bff   = (const float*)d_in[24];
    const float* Wfin  = (const float*)d_in[25];
    const float* bfin  = (const float*)d_in[26];
    float* out = (float*)d_out;

    // Symbol addresses (not stream ops; capture-safe)
    float *pX0, *pX0r, *pQkv, *pHeads, *pMh, *pX1, *pX1r, *pFF, *pFFo, *pX2r;
    float *pWqkv, *pBqkv, *pWproj, *pWff1, *pWff2, *pWfin, *pBfin;
    cudaGetSymbolAddress((void**)&pX0,    d_x0);
    cudaGetSymbolAddress((void**)&pX0r,   d_x0r);
    cudaGetSymbolAddress((void**)&pQkv,   d_qkvb);
    cudaGetSymbolAddress((void**)&pHeads, d_heads);
    cudaGetSymbolAddress((void**)&pMh,    d_mhb);
    cudaGetSymbolAddress((void**)&pX1,    d_x1);
    cudaGetSymbolAddress((void**)&pX1r,   d_x1r);
    cudaGetSymbolAddress((void**)&pFF,    d_ff);
    cudaGetSymbolAddress((void**)&pFFo,   d_ffo);
    cudaGetSymbolAddress((void**)&pX2r,   d_x2r);
    cudaGetSymbolAddress((void**)&pWqkv,  w_qkv);
    cudaGetSymbolAddress((void**)&pBqkv,  b_qkvp);
    cudaGetSymbolAddress((void**)&pWproj, w_proj);
    cudaGetSymbolAddress((void**)&pWff1,  w_ff1);
    cudaGetSymbolAddress((void**)&pWff2,  w_ff2);
    cudaGetSymbolAddress((void**)&pWfin,  w_fin);
    cudaGetSymbolAddress((void**)&pBfin,  b_finp);

    // dynamic smem limits
    const int SM128 = 2 * (128 * 36 + 128 * 36) * 4;   // 73728
    const int SM64  = 2 * (64 * 36 + 128 * 36) * 4;    // 55296
    const int SMATT = (3 * 43 * 97 + 43 * 44) * 4;     // 57620
    cudaFuncSetAttribute(gemm_tn<128, false, false>,
                         cudaFuncAttributeMaxDynamicSharedMemorySize, SM128);
    cudaFuncSetAttribute(gemm_tn<128, true, true>,
                         cudaFuncAttributeMaxDynamicSharedMemorySize, SM128);
    cudaFuncSetAttribute(gemm_tn<64, false, false>,
                         cudaFuncAttributeMaxDynamicSharedMemorySize, SM64);
    cudaFuncSetAttribute(attn_kernel,
                         cudaFuncAttributeMaxDynamicSharedMemorySize, SMATT);

    // --- weight prep ---
    pack_qkv_w_kernel<<<(QKVP * HH + 255) / 256, 256>>>(Wq1, Wk1, Wv1, Wq2, Wk2, Wv2);
    pack_qkv_b_kernel<<<3, 256>>>(bq1, bk1, bv1, bq2, bk2, bv2);
    round_copy_kernel<<<(HH * 192 + 255) / 256, 256>>>(pWproj, Wproj, HH * 192);
    round_copy_kernel<<<(DFF_ * HH + 255) / 256, 256>>>(pWff1, Wff1, DFF_ * HH);
    round_copy_kernel<<<(HH * DFF_ + 255) / 256, 256>>>(pWff2, Wff2, HH * DFF_);
    pack_fin_kernel<<<(OUTP * HH + 255) / 256, 256>>>(Wfin, bfin);

    // --- forward ---
    embed_kernel<<<(M_TOK * HH) / 256, 256>>>(inp, emb, pos);

    // QKV: [M,128] @ [576(pad640),128]^T
    gemm_tn<128, false, false><<<dim3(172, 5), 256, SM128>>>(
        pX0r, pWqkv, pBqkv, pQkv, 128, QKVW, QKVW);

    attn_kernel<<<dim3(NB, 2), 256, SMATT>>>(pQkv, pHeads);

    // proj: [M,192] @ [128,192]^T
    gemm_tn<64, false, false><<<dim3(344, 1), 256, SM64>>>(
        pHeads, pWproj, bproj, pMh, 192, HH, HH);

    add_ln_kernel<<<M_TOK / 8, 256>>>(pMh, pX0, gmh, bmh, pX1, pX1r);

    // FF1 + relu + round: [M,128] @ [2048,128]^T
    gemm_tn<128, true, true><<<dim3(172, 16), 256, SM128>>>(
        pX1r, pWff1, bff1, pFF, 128, DFF_, DFF_);

    // FF2: [M,2048] @ [128,2048]^T
    gemm_tn<64, false, false><<<dim3(344, 1), 256, SM64>>>(
        pFF, pWff2, bff2, pFFo, DFF_, HH, HH);

    add_ln_kernel<<<M_TOK / 8, 256>>>(pFFo, pX1, gff, bff, nullptr, pX2r);

    // Final: [M,128] @ [8000(pad8064),128]^T -> d_out
    gemm_tn<128, false, false><<<dim3(172, 63), 256, SM128>>>(
        pX2r, pWfin, pBfin, out, 128, OUTV, OUTV);
}

// round 14
// speedup vs baseline: 1.3771x; 1.3771x over previous
#include <cuda_runtime.h>
#include <cuda_fp16.h>
#include <math.h>
#include <cstdint>

// ---------------------------------------------------------------------------
// Problem constants
// ---------------------------------------------------------------------------
#define M_TOK 22016   // N*T = 512*43
#define NB    512
#define TT    43
#define HH    128
#define DKH   96
#define DFF_  2048
#define OUTV  8000
#define OUTP  8064    // padded to multiple of 128
#define QKVW  576     // 6*96 packed
#define QKVP  640     // padded to multiple of 128

// ---------------------------------------------------------------------------
// Device-global scratch (no allocation allowed)
// ---------------------------------------------------------------------------
__device__ float  d_x0  [M_TOK * HH];      // embed, exact fp32
__device__ __half d_x0h [M_TOK * HH];      // embed, fp16
__device__ float  d_qkvb[M_TOK * QKVW];    // packed q1 k1 v1 q2 k2 v2 (fp32)
__device__ __half d_heads[M_TOK * 192];    // concat(h1,h2), fp16
__device__ float  d_mhb [M_TOK * HH];      // proj output
__device__ float  d_x1  [M_TOK * HH];      // LN1 out exact
__device__ __half d_x1h [M_TOK * HH];      // LN1 out fp16
__device__ __half d_ff  [M_TOK * DFF_];    // relu(ff1), fp16
__device__ float  d_ffo [M_TOK * HH];      // ff2 output
__device__ __half d_x2h [M_TOK * HH];      // LN2 out fp16

__device__ __half w_qkv [QKVP * HH];       // packed+padded fp16
__device__ float  b_qkvp[QKVP];
__device__ __half w_proj[HH * 192];
__device__ __half w_ff1 [DFF_ * HH];
__device__ __half w_ff2 [HH * DFF_];
__device__ __half w_fin [OUTP * HH];       // padded rows zeroed
__device__ float  b_finp[OUTP];

// ---------------------------------------------------------------------------
// Helpers
// ---------------------------------------------------------------------------
__device__ __forceinline__ unsigned int smem_u32(const void* p) {
    return (unsigned int)__cvta_generic_to_shared(p);
}
__device__ __forceinline__ void cp16(unsigned int dst, const void* src) {
    asm volatile("cp.async.cg.shared.global [%0], [%1], 16;\n" :: "r"(dst), "l"(src));
}
__device__ __forceinline__ void mma_f16(float (&d)[4], const unsigned int (&a)[4],
                                        const unsigned int (&b)[2]) {
    asm volatile(
        "mma.sync.aligned.m16n8k16.row.col.f32.f16.f16.f32 "
        "{%0,%1,%2,%3},{%4,%5,%6,%7},{%8,%9},{%0,%1,%2,%3};"
        : "+f"(d[0]), "+f"(d[1]), "+f"(d[2]), "+f"(d[3])
        : "r"(a[0]), "r"(a[1]), "r"(a[2]), "r"(a[3]), "r"(b[0]), "r"(b[1]));
}

// ---------------------------------------------------------------------------
// fp16 GEMM: C[M,N] = A[M,K] @ B[N,K]^T + bias (fp32 accumulate).
// CTA tile 128x128, BK=64 halves, 2-stage cp.async. 256 threads = 8 warps
// as 2(M) x 4(N); warp tile 64x32. smem row pitch 72 halves => all fragment
// LDS.32 conflict-free. B rows must cover n0..n0+127 (weights padded);
// stores masked col < Nstore. K must be a multiple of 64.
// ---------------------------------------------------------------------------
template <typename OutT, bool RELU>
__global__ void __launch_bounds__(256, 1)
gemm_h(const __half* __restrict__ A, const __half* __restrict__ B,
       const float* __restrict__ bias, OutT* __restrict__ C,
       int K, int ldc, int Nstore)
{
    constexpr int LDH = 72;                 // halves per smem row
    constexpr int STG = 256 * LDH;          // halves per stage (A 128 + B 128 rows)
    extern __shared__ __half smh[];

    const int tid  = threadIdx.x;
    const int wid  = tid >> 5;
    const int lane = tid & 31;
    const int wr   = wid >> 2;              // 0..1
    const int wc   = wid & 3;               // 0..3
    const int g    = lane >> 2;             // 0..7
    const int tg   = lane & 3;              // 0..3

    const int KT = K >> 6;                  // K chunks of 64
    const __half* Ab = A + (size_t)blockIdx.x * 128 * K;
    const __half* Bb = B + (size_t)blockIdx.y * 128 * K;

    float acc[4][4][4];
#pragma unroll
    for (int i = 0; i < 4; i++)
#pragma unroll
        for (int j = 0; j < 4; j++)
#pragma unroll
            for (int q = 0; q < 4; q++) acc[i][j][q] = 0.f;

    auto load_stage = [&](int buf, int kt) {
        const unsigned int ab = smem_u32(smh + buf * STG);
        const unsigned int bb = ab + 128 * LDH * 2;
        const int kof = kt * 64;
#pragma unroll
        for (int i = 0; i < 4; i++) {
            int t = tid + 256 * i;
            int row = t >> 3, c = t & 7;
            cp16(ab + (unsigned)(row * LDH + c * 8) * 2,
                 Ab + (size_t)row * K + kof + c * 8);
        }
#pragma unroll
        for (int i = 0; i < 4; i++) {
            int t = tid + 256 * i;
            int row = t >> 3, c = t & 7;
            cp16(bb + (unsigned)(row * LDH + c * 8) * 2,
                 Bb + (size_t)row * K + kof + c * 8);
        }
        asm volatile("cp.async.commit_group;" ::);
    };

    load_stage(0, 0);
    for (int kt = 0; kt < KT; ++kt) {
        const int buf = kt & 1;
        asm volatile("cp.async.wait_group 0;" ::);
        __syncthreads();
        if (kt + 1 < KT) load_stage(buf ^ 1, kt + 1);

        const __half* Aw = smh + buf * STG + (wr * 64 + g) * LDH + 2 * tg;
        const __half* Bw = smh + buf * STG + 128 * LDH + (wc * 32 + g) * LDH + 2 * tg;
#pragma unroll
        for (int ks = 0; ks < 4; ++ks) {
            const int k0 = ks * 16;
            unsigned int a[4][4], b[4][2];
#pragma unroll
            for (int mf = 0; mf < 4; ++mf) {
                const __half* p = Aw + mf * 16 * LDH + k0;
                a[mf][0] = *reinterpret_cast<const unsigned int*>(p);
                a[mf][1] = *reinterpret_cast<const unsigned int*>(p + 8 * LDH);
                a[mf][2] = *reinterpret_cast<const unsigned int*>(p + 8);
                a[mf][3] = *reinterpret_cast<const unsigned int*>(p + 8 * LDH + 8);
            }
#pragma unroll
            for (int nf = 0; nf < 4; ++nf) {
                const __half* p = Bw + nf * 8 * LDH + k0;
                b[nf][0] = *reinterpret_cast<const unsigned int*>(p);
                b[nf][1] = *reinterpret_cast<const unsigned int*>(p + 8);
            }
#pragma unroll
            for (int mf = 0; mf < 4; ++mf)
#pragma unroll
                for (int nf = 0; nf < 4; ++nf)
                    mma_f16(acc[mf][nf], a[mf], b[nf]);
        }
        __syncthreads();
    }

    // Epilogue: c0@(g, 2tg) c1@(g, 2tg+1) c2@(g+8, 2tg) c3@(g+8, 2tg+1)
    const int n0 = blockIdx.y * 128;
#pragma unroll
    for (int mf = 0; mf < 4; ++mf) {
#pragma unroll
        for (int nf = 0; nf < 4; ++nf) {
            const int c = n0 + wc * 32 + nf * 8 + tg * 2;
            if (c < Nstore) {
                const float bi0 = bias[c];
                const float bi1 = bias[c + 1];
#pragma unroll
                for (int h = 0; h < 2; ++h) {
                    const int r = blockIdx.x * 128 + wr * 64 + mf * 16 + g + h * 8;
                    float v0 = acc[mf][nf][h * 2 + 0] + bi0;
                    float v1 = acc[mf][nf][h * 2 + 1] + bi1;
                    if (RELU) { v0 = fmaxf(v0, 0.f); v1 = fmaxf(v1, 0.f); }
                    OutT* dst = C + (size_t)r * ldc + c;
                    if (sizeof(OutT) == 4) {
                        float2 val; val.x = v0; val.y = v1;
                        *reinterpret_cast<float2*>(dst) = val;
                    } else {
                        __half2 hv = __floats2half2_rn(v0, v1);
                        *reinterpret_cast<__half2*>(dst) = hv;
                    }
                }
            }
        }
    }
}

// ---------------------------------------------------------------------------
// Attention: one CTA per (batch, head). All fp32 in smem; fp16 output.
// ---------------------------------------------------------------------------
__global__ void __launch_bounds__(256, 1)
attn_kernel(const float* __restrict__ qkv, __half* __restrict__ heads)
{
    extern __shared__ float sm[];
    float* q  = sm;                 // 43*97
    float* k  = q + 43 * 97;
    float* v  = k + 43 * 97;
    float* sc = v + 43 * 97;        // 43*44

    const int n = blockIdx.x, head = blockIdx.y;
    const int tid = threadIdx.x;
    const float* base = qkv + (size_t)(n * TT) * QKVW + head * 288;

    for (int idx = tid; idx < TT * DKH; idx += 256) {
        int i = idx / DKH, d = idx - i * DKH;
        const float* row = base + (size_t)i * QKVW;
        q[i * 97 + d] = row[d];
        k[i * 97 + d] = row[96 + d];
        v[i * 97 + d] = row[192 + d];
    }
    __syncthreads();

    const float scale = 0.10206207261596577f;   // 1/sqrt(96)
    for (int p = tid; p < TT * TT; p += 256) {
        int i = p / TT, j = p - i * TT;
        float s = 0.f;
#pragma unroll 16
        for (int d = 0; d < DKH; ++d) s += q[i * 97 + d] * k[j * 97 + d];
        sc[i * 44 + j] = s * scale;
    }
    __syncthreads();

    const int warpId = tid >> 5, lane = tid & 31;
    for (int i = warpId; i < TT; i += 8) {
        float x0 = (lane < TT)      ? sc[i * 44 + lane]      : -1e30f;
        float x1 = (lane + 32 < TT) ? sc[i * 44 + lane + 32] : -1e30f;
        float m = fmaxf(x0, x1);
#pragma unroll
        for (int o = 16; o; o >>= 1) m = fmaxf(m, __shfl_xor_sync(0xffffffffu, m, o));
        float e0 = (lane < TT)      ? expf(x0 - m) : 0.f;
        float e1 = (lane + 32 < TT) ? expf(x1 - m) : 0.f;
        float s = e0 + e1;
#pragma unroll
        for (int o = 16; o; o >>= 1) s += __shfl_xor_sync(0xffffffffu, s, o);
        float inv = 1.f / s;
        if (lane < TT)      sc[i * 44 + lane]      = e0 * inv;
        if (lane + 32 < TT) sc[i * 44 + lane + 32] = e1 * inv;
    }
    __syncthreads();

    __half* out = heads + (size_t)(n * TT) * 192 + head * 96;
    for (int idx = tid; idx < TT * DKH; idx += 256) {
        int i = idx / DKH, d = idx - i * DKH;
        float o = 0.f;
#pragma unroll
        for (int j = 0; j < TT; ++j) o += sc[i * 44 + j] * v[j * 97 + d];
        out[(size_t)i * 192 + d] = __float2half_rn(o);
    }
}

// ---------------------------------------------------------------------------
// Fused add + LayerNorm. One warp per token; exact fp32 + fp16 outputs.
// ---------------------------------------------------------------------------
__global__ void __launch_bounds__(256, 1)
add_ln_kernel(const float* __restrict__ a, const float* __restrict__ res,
              const float* __restrict__ gam, const float* __restrict__ bet,
              float* __restrict__ outE, __half* __restrict__ outH)
{
    const int warpId = threadIdx.x >> 5, lane = threadIdx.x & 31;
    const int m = blockIdx.x * 8 + warpId;
    const float* ap = a   + (size_t)m * HH;
    const float* rp = res + (size_t)m * HH;
    float x[4];
    float s = 0.f, ss = 0.f;
#pragma unroll
    for (int q = 0; q < 4; q++) {
        x[q] = ap[lane + 32 * q] + rp[lane + 32 * q];
        s += x[q]; ss += x[q] * x[q];
    }
#pragma unroll
    for (int o = 16; o; o >>= 1) {
        s  += __shfl_xor_sync(0xffffffffu, s,  o);
        ss += __shfl_xor_sync(0xffffffffu, ss, o);
    }
    const float mean = s * (1.f / 128.f);
    const float var  = ss * (1.f / 128.f) - mean * mean;
    const float rstd = rsqrtf(var + 1e-5f);
#pragma unroll
    for (int q = 0; q < 4; q++) {
        const int h = lane + 32 * q;
        const float y = (x[q] - mean) * rstd * gam[h] + bet[h];
        if (outE) outE[(size_t)m * HH + h] = y;
        outH[(size_t)m * HH + h] = __float2half_rn(y);
    }
}

// ---------------------------------------------------------------------------
// Embedding: word + positional, exact fp32 + fp16 copies.
// ---------------------------------------------------------------------------
__global__ void embed_kernel(const int* __restrict__ inp,
                             const float* __restrict__ emb,
                             const float* __restrict__ pos)
{
    const int idx = blockIdx.x * 256 + threadIdx.x;     // < M_TOK*128
    const int m = idx >> 7, h = idx & 127;
    const int t = m % TT;
    const int id = inp[m];
    const float v = emb[(size_t)id * HH + h] + pos[t * HH + h];
    d_x0[idx]  = v;
    d_x0h[idx] = __float2half_rn(v);
}

// ---------------------------------------------------------------------------
// Weight prep kernels (run every call; cheap, graph-capturable)
// ---------------------------------------------------------------------------
__global__ void round_all_kernel(const float* __restrict__ Wp,
                                 const float* __restrict__ W1,
                                 const float* __restrict__ W2)
{
    const int i = blockIdx.x * 256 + threadIdx.x;
    const int n1 = HH * 192, n2 = DFF_ * HH, n3 = HH * DFF_;
    if (i < n1)                w_proj[i]          = __float2half_rn(Wp[i]);
    else if (i < n1 + n2)      w_ff1[i - n1]      = __float2half_rn(W1[i - n1]);
    else if (i < n1 + n2 + n3) w_ff2[i - n1 - n2] = __float2half_rn(W2[i - n1 - n2]);
}

__global__ void pack_qkv_w_kernel(const float* __restrict__ Wq1, const float* __restrict__ Wk1,
                                  const float* __restrict__ Wv1, const float* __restrict__ Wq2,
                                  const float* __restrict__ Wk2, const float* __restrict__ Wv2)
{
    const int idx = blockIdx.x * 256 + threadIdx.x;
    if (idx >= QKVP * HH) return;
    const int r = idx >> 7, c = idx & 127;
    float v = 0.f;
    if (r < QKVW) {
        const int sel = r / 96, rr = r - sel * 96;
        const float* W = sel == 0 ? Wq1 : sel == 1 ? Wk1 : sel == 2 ? Wv1
                       : sel == 3 ? Wq2 : sel == 4 ? Wk2 : Wv2;
        v = W[rr * HH + c];
    }
    w_qkv[idx] = __float2half_rn(v);
}

__global__ void pack_qkv_b_kernel(const float* __restrict__ bq1, const float* __restrict__ bk1,
                                  const float* __restrict__ bv1, const float* __restrict__ bq2,
                                  const float* __restrict__ bk2, const float* __restrict__ bv2)
{
    const int i = blockIdx.x * 256 + threadIdx.x;
    if (i >= QKVP) return;
    float v = 0.f;
    if (i < QKVW) {
        const int sel = i / 96, rr = i - sel * 96;
        const float* b = sel == 0 ? bq1 : sel == 1 ? bk1 : sel == 2 ? bv1
                       : sel == 3 ? bq2 : sel == 4 ? bk2 : bv2;
        v = b[rr];
    }
    b_qkvp[i] = v;
}

__global__ void pack_fin_kernel(const float* __restrict__ W, const float* __restrict__ b)
{
    const int idx = blockIdx.x * 256 + threadIdx.x;
    if (idx < OUTP * HH) {
        const int r = idx >> 7;
        w_fin[idx] = __float2half_rn((r < OUTV) ? W[idx] : 0.f);
    }
    if (idx < OUTP) b_finp[idx] = (idx < OUTV) ? b[idx] : 0.f;
}

// ---------------------------------------------------------------------------
// Launch
// ---------------------------------------------------------------------------
extern "C" void kernel_launch(void* const* d_in, const int* in_sizes, int n_in,
                              void* d_out, int out_size)
{
    const int*   inp   = (const int*)  d_in[0];
    const float* emb   = (const float*)d_in[1];
    const float* pos   = (const float*)d_in[2];
    const float* Wk1   = (const float*)d_in[3];
    const float* bk1   = (const float*)d_in[4];
    const float* Wv1   = (const float*)d_in[5];
    const float* bv1   = (const float*)d_in[6];
    const float* Wq1   = (const float*)d_in[7];
    const float* bq1   = (const float*)d_in[8];
    const float* Wk2   = (const float*)d_in[9];
    const float* bk2   = (const float*)d_in[10];
    const float* Wv2   = (const float*)d_in[11];
    const float* bv2   = (const float*)d_in[12];
    const float* Wq2   = (const float*)d_in[13];
    const float* bq2   = (const float*)d_in[14];
    const float* Wproj = (const float*)d_in[15];
    const float* bproj = (const float*)d_in[16];
    const float* gmh   = (const float*)d_in[17];
    const float* bmh   = (const float*)d_in[18];
    const float* Wff1  = (const float*)d_in[19];
    const float* bff1  = (const float*)d_in[20];
    const float* Wff2  = (const float*)d_in[21];
    const float* bff2  = (const float*)d_in[22];
    const float* gff   = (const float*)d_in[23];
    const float* bff   = (const float*)d_in[24];
    const float* Wfin  = (const float*)d_in[25];
    const float* bfin  = (const float*)d_in[26];
    float* out = (float*)d_out;

    float  *pX0, *pQkv, *pMh, *pX1, *pFFo;
    __half *pX0h, *pHeads, *pX1h, *pFF, *pX2h;
    __half *pWqkv, *pWproj, *pWff1, *pWff2, *pWfin;
    float  *pBqkv, *pBfin;
    cudaGetSymbolAddress((void**)&pX0,    d_x0);
    cudaGetSymbolAddress((void**)&pX0h,   d_x0h);
    cudaGetSymbolAddress((void**)&pQkv,   d_qkvb);
    cudaGetSymbolAddress((void**)&pHeads, d_heads);
    cudaGetSymbolAddress((void**)&pMh,    d_mhb);
    cudaGetSymbolAddress((void**)&pX1,    d_x1);
    cudaGetSymbolAddress((void**)&pX1h,   d_x1h);
    cudaGetSymbolAddress((void**)&pFF,    d_ff);
    cudaGetSymbolAddress((void**)&pFFo,   d_ffo);
    cudaGetSymbolAddress((void**)&pX2h,   d_x2h);
    cudaGetSymbolAddress((void**)&pWqkv,  w_qkv);
    cudaGetSymbolAddress((void**)&pBqkv,  b_qkvp);
    cudaGetSymbolAddress((void**)&pWproj, w_proj);
    cudaGetSymbolAddress((void**)&pWff1,  w_ff1);
    cudaGetSymbolAddress((void**)&pWff2,  w_ff2);
    cudaGetSymbolAddress((void**)&pWfin,  w_fin);
    cudaGetSymbolAddress((void**)&pBfin,  b_finp);

    const int SMGEMM = 2 * 256 * 72 * 2;               // 73728 bytes (2 stages)
    const int SMATT  = (3 * 43 * 97 + 43 * 44) * 4;    // 57620 bytes
    cudaFuncSetAttribute(gemm_h<float, false>,
                         cudaFuncAttributeMaxDynamicSharedMemorySize, SMGEMM);
    cudaFuncSetAttribute(gemm_h<__half, true>,
                         cudaFuncAttributeMaxDynamicSharedMemorySize, SMGEMM);
    cudaFuncSetAttribute(attn_kernel,
                         cudaFuncAttributeMaxDynamicSharedMemorySize, SMATT);

    // --- weight prep (launches 1..4) ---
    pack_qkv_w_kernel<<<(QKVP * HH + 255) / 256, 256>>>(Wq1, Wk1, Wv1, Wq2, Wk2, Wv2);
    pack_qkv_b_kernel<<<3, 256>>>(bq1, bk1, bv1, bq2, bk2, bv2);
    round_all_kernel<<<(HH * 192 + DFF_ * HH + HH * DFF_ + 255) / 256, 256>>>(Wproj, Wff1, Wff2);
    pack_fin_kernel<<<(OUTP * HH + 255) / 256, 256>>>(Wfin, bfin);

    // --- forward ---
    embed_kernel<<<(M_TOK * HH) / 256, 256>>>(inp, emb, pos);           // launch 5

    // QKV: [M,128] @ [576(pad640),128]^T  -> fp32                        launch 6 (profiled)
    gemm_h<float, false><<<dim3(172, 5), 256, SMGEMM>>>(
        pX0h, pWqkv, pBqkv, pQkv, 128, QKVW, QKVW);

    attn_kernel<<<dim3(NB, 2), 256, SMATT>>>(pQkv, pHeads);

    // proj: [M,192] @ [128,192]^T -> fp32
    gemm_h<float, false><<<dim3(172, 1), 256, SMGEMM>>>(
        pHeads, pWproj, bproj, pMh, 192, HH, HH);

    add_ln_kernel<<<M_TOK / 8, 256>>>(pMh, pX0, gmh, bmh, pX1, pX1h);

    // FF1 + relu -> fp16: [M,128] @ [2048,128]^T
    gemm_h<__half, true><<<dim3(172, 16), 256, SMGEMM>>>(
        pX1h, pWff1, bff1, pFF, 128, DFF_, DFF_);

    // FF2: [M,2048] @ [128,2048]^T -> fp32
    gemm_h<float, false><<<dim3(172, 1), 256, SMGEMM>>>(
        pFF, pWff2, bff2, pFFo, DFF_, HH, HH);

    add_ln_kernel<<<M_TOK / 8, 256>>>(pFFo, pX1, gff, bff, nullptr, pX2h);

    // Final: [M,128] @ [8000(pad8064),128]^T -> d_out (fp32)
    gemm_h<float, false><<<dim3(172, 63), 256, SMGEMM>>>(
        pX2h, pWfin, pBfin, out, 128, OUTV, OUTV);
}

// round 15
// speedup vs baseline: 1.4917x; 1.0832x over previous
#include <cuda_runtime.h>
#include <cuda_fp16.h>
#include <math.h>
#include <cstdint>

// ---------------------------------------------------------------------------
// Problem constants
// ---------------------------------------------------------------------------
#define M_TOK 22016   // N*T = 512*43
#define NB    512
#define TT    43
#define HH    128
#define DKH   96
#define DFF_  2048
#define OUTV  8000
#define OUTP  8192    // padded to multiple of 256
#define QKVW  576     // 6*96 packed
#define QKVP  768     // padded to multiple of 256

// ---------------------------------------------------------------------------
// Device-global scratch (no allocation allowed)
// ---------------------------------------------------------------------------
__device__ float  d_x0  [M_TOK * HH];      // embed, exact fp32
__device__ __half d_x0h [M_TOK * HH];      // embed, fp16
__device__ float  d_qkvb[M_TOK * QKVW];    // packed q1 k1 v1 q2 k2 v2 (fp32)
__device__ __half d_heads[M_TOK * 192];    // concat(h1,h2), fp16
__device__ float  d_mhb [M_TOK * HH];      // proj output
__device__ float  d_x1  [M_TOK * HH];      // LN1 out exact
__device__ __half d_x1h [M_TOK * HH];      // LN1 out fp16
__device__ __half d_ff  [M_TOK * DFF_];    // relu(ff1), fp16
__device__ float  d_ffo [M_TOK * HH];      // ff2 output
__device__ __half d_x2h [M_TOK * HH];      // LN2 out fp16

__device__ __half w_qkv [QKVP * HH];       // packed+padded fp16
__device__ float  b_qkvp[QKVP];
__device__ __half w_proj[HH * 192];
__device__ __half w_ff1 [DFF_ * HH];
__device__ __half w_ff2 [HH * DFF_];
__device__ __half w_fin [OUTP * HH];       // padded rows zeroed
__device__ float  b_finp[OUTP];

// ---------------------------------------------------------------------------
// Helpers
// ---------------------------------------------------------------------------
__device__ __forceinline__ unsigned int smem_u32(const void* p) {
    return (unsigned int)__cvta_generic_to_shared(p);
}
__device__ __forceinline__ void cp16(unsigned int dst, const void* src) {
    asm volatile("cp.async.cg.shared.global [%0], [%1], 16;\n" :: "r"(dst), "l"(src));
}
__device__ __forceinline__ void mma_f16(float (&d)[4], const unsigned int (&a)[4],
                                        const unsigned int (&b)[2]) {
    asm volatile(
        "mma.sync.aligned.m16n8k16.row.col.f32.f16.f16.f32 "
        "{%0,%1,%2,%3},{%4,%5,%6,%7},{%8,%9},{%0,%1,%2,%3};"
        : "+f"(d[0]), "+f"(d[1]), "+f"(d[2]), "+f"(d[3])
        : "r"(a[0]), "r"(a[1]), "r"(a[2]), "r"(a[3]), "r"(b[0]), "r"(b[1]));
}
__device__ __forceinline__ void ldsm4(unsigned int& r0, unsigned int& r1,
                                      unsigned int& r2, unsigned int& r3,
                                      unsigned int addr) {
    asm volatile("ldmatrix.sync.aligned.m8n8.x4.shared.b16 {%0,%1,%2,%3}, [%4];"
                 : "=r"(r0), "=r"(r1), "=r"(r2), "=r"(r3) : "r"(addr));
}

// ---------------------------------------------------------------------------
// fp16 GEMM via ldmatrix + mma.m16n8k16, fp32 accumulate.
// C[M,N] = A[M,K] @ B[N,K]^T + bias. CTA tile 128 x NT (NT = 128 or 256),
// BK = 64 halves, 3-stage cp.async pipeline (wait_group 1). 256 threads =
// 8 warps as 2(M) x 4(N); warp tile 64 x NT/4. smem pitch 72 halves =>
// cp.async stores, ldmatrix reads all conflict-free. B rows must cover
// n0..n0+NT-1 (weights padded); stores masked col < Nstore. K % 64 == 0.
// ---------------------------------------------------------------------------
template <int NT, typename OutT, bool RELU>
__global__ void __launch_bounds__(256, 1)
gemm_ldsm(const __half* __restrict__ A, const __half* __restrict__ B,
          const float* __restrict__ bias, OutT* __restrict__ C,
          int K, int ldc, int Nstore)
{
    constexpr int LDH = 72;                    // halves per smem row
    constexpr int STG = (128 + NT) * LDH;      // halves per stage
    constexpr int NF  = NT / 32;               // n-frags per warp (4 or 8)
    constexpr int NP  = NF / 2;                // ldmatrix B pairs
    extern __shared__ __half smh[];

    const int tid  = threadIdx.x;
    const int wid  = tid >> 5;
    const int lane = tid & 31;
    const int wr   = wid >> 2;                 // 0..1
    const int wc   = wid & 3;                  // 0..3
    const int g    = lane >> 2;                // 0..7
    const int tg   = lane & 3;                 // 0..3

    const int KT = K >> 6;
    const __half* Ab = A + (size_t)blockIdx.x * 128 * K;
    const __half* Bb = B + (size_t)blockIdx.y * NT * K;

    float acc[4][NF][4];
#pragma unroll
    for (int i = 0; i < 4; i++)
#pragma unroll
        for (int j = 0; j < NF; j++)
#pragma unroll
            for (int q = 0; q < 4; q++) acc[i][j][q] = 0.f;

    const unsigned int sb = smem_u32(smh);

    auto load_stage = [&](int buf, int kt) {
        const unsigned int ab = sb + (unsigned)buf * STG * 2;
        const unsigned int bb = ab + 128 * LDH * 2;
        const int kof = kt * 64;
#pragma unroll
        for (int i = 0; i < 4; i++) {
            int t = tid + 256 * i;
            int row = t >> 3, c = t & 7;
            cp16(ab + (unsigned)(row * LDH + c * 8) * 2,
                 Ab + (size_t)row * K + kof + c * 8);
        }
#pragma unroll
        for (int i = 0; i < NT / 32; i++) {
            int t = tid + 256 * i;
            int row = t >> 3, c = t & 7;
            cp16(bb + (unsigned)(row * LDH + c * 8) * 2,
                 Bb + (size_t)row * K + kof + c * 8);
        }
        asm volatile("cp.async.commit_group;" ::);
    };

    // ldmatrix per-lane address components: matrix = lane>>3
    const int mrow = (lane & 7) + ((lane >> 3) & 1) * 8;   // row within 16
    const int mcol = (lane >> 4) * 8;                      // k-half offset
    const unsigned int a_off = (unsigned)((wr * 64 + mrow) * LDH + mcol) * 2;
    const unsigned int b_off = (unsigned)(128 * LDH + (wc * (NT / 4) + mrow) * LDH + mcol) * 2;

    load_stage(0, 0);
    if (KT > 1) load_stage(1, 1);

    for (int kc = 0; kc < KT; ++kc) {
        if (kc + 1 < KT) asm volatile("cp.async.wait_group 1;" ::);
        else             asm volatile("cp.async.wait_group 0;" ::);
        __syncthreads();
        if (kc + 2 < KT) load_stage((kc + 2) % 3, kc + 2);

        const unsigned int stg = sb + (unsigned)((kc % 3) * STG) * 2;
#pragma unroll
        for (int ks = 0; ks < 4; ++ks) {
            const unsigned int kb = (unsigned)(ks * 16) * 2;
            unsigned int a[4][4], b[NF][2];
#pragma unroll
            for (int mf = 0; mf < 4; ++mf)
                ldsm4(a[mf][0], a[mf][1], a[mf][2], a[mf][3],
                      stg + a_off + (unsigned)(mf * 16 * LDH) * 2 + kb);
#pragma unroll
            for (int p = 0; p < NP; ++p)
                ldsm4(b[2 * p][0], b[2 * p + 1][0], b[2 * p][1], b[2 * p + 1][1],
                      stg + b_off + (unsigned)(p * 16 * LDH) * 2 + kb);
#pragma unroll
            for (int mf = 0; mf < 4; ++mf)
#pragma unroll
                for (int nf = 0; nf < NF; ++nf)
                    mma_f16(acc[mf][nf], a[mf], b[nf]);
        }
        // buffer (kc%3) is reused by load at iter kc+1, which happens after
        // that iteration's __syncthreads -- no trailing sync needed.
    }

    // Epilogue: c0@(g, 2tg) c1@(g, 2tg+1) c2@(g+8, 2tg) c3@(g+8, 2tg+1)
    const int n0 = blockIdx.y * NT;
#pragma unroll
    for (int mf = 0; mf < 4; ++mf) {
#pragma unroll
        for (int nf = 0; nf < NF; ++nf) {
            const int c = n0 + wc * (NT / 4) + nf * 8 + tg * 2;
            if (c < Nstore) {
                const float bi0 = bias[c];
                const float bi1 = bias[c + 1];
#pragma unroll
                for (int h = 0; h < 2; ++h) {
                    const int r = blockIdx.x * 128 + wr * 64 + mf * 16 + g + h * 8;
                    float v0 = acc[mf][nf][h * 2 + 0] + bi0;
                    float v1 = acc[mf][nf][h * 2 + 1] + bi1;
                    if (RELU) { v0 = fmaxf(v0, 0.f); v1 = fmaxf(v1, 0.f); }
                    OutT* dst = C + (size_t)r * ldc + c;
                    if (sizeof(OutT) == 4) {
                        float2 val; val.x = v0; val.y = v1;
                        *reinterpret_cast<float2*>(dst) = val;
                    } else {
                        __half2 hv = __floats2half2_rn(v0, v1);
                        *reinterpret_cast<__half2*>(dst) = hv;
                    }
                }
            }
        }
    }
}

// ---------------------------------------------------------------------------
// Attention: one CTA per (batch, head). All fp32 in smem; fp16 output.
// ---------------------------------------------------------------------------
__global__ void __launch_bounds__(256, 1)
attn_kernel(const float* __restrict__ qkv, __half* __restrict__ heads)
{
    extern __shared__ float sm[];
    float* q  = sm;                 // 43*97
    float* k  = q + 43 * 97;
    float* v  = k + 43 * 97;
    float* sc = v + 43 * 97;        // 43*44

    const int n = blockIdx.x, head = blockIdx.y;
    const int tid = threadIdx.x;
    const float* base = qkv + (size_t)(n * TT) * QKVW + head * 288;

    for (int idx = tid; idx < TT * DKH; idx += 256) {
        int i = idx / DKH, d = idx - i * DKH;
        const float* row = base + (size_t)i * QKVW;
        q[i * 97 + d] = row[d];
        k[i * 97 + d] = row[96 + d];
        v[i * 97 + d] = row[192 + d];
    }
    __syncthreads();

    const float scale = 0.10206207261596577f;   // 1/sqrt(96)
    for (int p = tid; p < TT * TT; p += 256) {
        int i = p / TT, j = p - i * TT;
        float s = 0.f;
#pragma unroll 16
        for (int d = 0; d < DKH; ++d) s += q[i * 97 + d] * k[j * 97 + d];
        sc[i * 44 + j] = s * scale;
    }
    __syncthreads();

    const int warpId = tid >> 5, lane = tid & 31;
    for (int i = warpId; i < TT; i += 8) {
        float x0 = (lane < TT)      ? sc[i * 44 + lane]      : -1e30f;
        float x1 = (lane + 32 < TT) ? sc[i * 44 + lane + 32] : -1e30f;
        float m = fmaxf(x0, x1);
#pragma unroll
        for (int o = 16; o; o >>= 1) m = fmaxf(m, __shfl_xor_sync(0xffffffffu, m, o));
        float e0 = (lane < TT)      ? expf(x0 - m) : 0.f;
        float e1 = (lane + 32 < TT) ? expf(x1 - m) : 0.f;
        float s = e0 + e1;
#pragma unroll
        for (int o = 16; o; o >>= 1) s += __shfl_xor_sync(0xffffffffu, s, o);
        float inv = 1.f / s;
        if (lane < TT)      sc[i * 44 + lane]      = e0 * inv;
        if (lane + 32 < TT) sc[i * 44 + lane + 32] = e1 * inv;
    }
    __syncthreads();

    __half* out = heads + (size_t)(n * TT) * 192 + head * 96;
    for (int idx = tid; idx < TT * DKH; idx += 256) {
        int i = idx / DKH, d = idx - i * DKH;
        float o = 0.f;
#pragma unroll
        for (int j = 0; j < TT; ++j) o += sc[i * 44 + j] * v[j * 97 + d];
        out[(size_t)i * 192 + d] = __float2half_rn(o);
    }
}

// ---------------------------------------------------------------------------
// Fused add + LayerNorm. One warp per token; exact fp32 + fp16 outputs.
// ---------------------------------------------------------------------------
__global__ void __launch_bounds__(256, 1)
add_ln_kernel(const float* __restrict__ a, const float* __restrict__ res,
              const float* __restrict__ gam, const float* __restrict__ bet,
              float* __restrict__ outE, __half* __restrict__ outH)
{
    const int warpId = threadIdx.x >> 5, lane = threadIdx.x & 31;
    const int m = blockIdx.x * 8 + warpId;
    const float* ap = a   + (size_t)m * HH;
    const float* rp = res + (size_t)m * HH;
    float x[4];
    float s = 0.f, ss = 0.f;
#pragma unroll
    for (int q = 0; q < 4; q++) {
        x[q] = ap[lane + 32 * q] + rp[lane + 32 * q];
        s += x[q]; ss += x[q] * x[q];
    }
#pragma unroll
    for (int o = 16; o; o >>= 1) {
        s  += __shfl_xor_sync(0xffffffffu, s,  o);
        ss += __shfl_xor_sync(0xffffffffu, ss, o);
    }
    const float mean = s * (1.f / 128.f);
    const float var  = ss * (1.f / 128.f) - mean * mean;
    const float rstd = rsqrtf(var + 1e-5f);
#pragma unroll
    for (int q = 0; q < 4; q++) {
        const int h = lane + 32 * q;
        const float y = (x[q] - mean) * rstd * gam[h] + bet[h];
        if (outE) outE[(size_t)m * HH + h] = y;
        outH[(size_t)m * HH + h] = __float2half_rn(y);
    }
}

// ---------------------------------------------------------------------------
// Embedding: word + positional, exact fp32 + fp16 copies.
// ---------------------------------------------------------------------------
__global__ void embed_kernel(const int* __restrict__ inp,
                             const float* __restrict__ emb,
                             const float* __restrict__ pos)
{
    const int idx = blockIdx.x * 256 + threadIdx.x;     // < M_TOK*128
    const int m = idx >> 7, h = idx & 127;
    const int t = m % TT;
    const int id = inp[m];
    const float v = emb[(size_t)id * HH + h] + pos[t * HH + h];
    d_x0[idx]  = v;
    d_x0h[idx] = __float2half_rn(v);
}

// ---------------------------------------------------------------------------
// Weight prep kernels (run every call; cheap, graph-capturable)
// ---------------------------------------------------------------------------
__global__ void round_all_kernel(const float* __restrict__ Wp,
                                 const float* __restrict__ W1,
                                 const float* __restrict__ W2)
{
    const int i = blockIdx.x * 256 + threadIdx.x;
    const int n1 = HH * 192, n2 = DFF_ * HH, n3 = HH * DFF_;
    if (i < n1)                w_proj[i]          = __float2half_rn(Wp[i]);
    else if (i < n1 + n2)      w_ff1[i - n1]      = __float2half_rn(W1[i - n1]);
    else if (i < n1 + n2 + n3) w_ff2[i - n1 - n2] = __float2half_rn(W2[i - n1 - n2]);
}

__global__ void pack_qkv_w_kernel(const float* __restrict__ Wq1, const float* __restrict__ Wk1,
                                  const float* __restrict__ Wv1, const float* __restrict__ Wq2,
                                  const float* __restrict__ Wk2, const float* __restrict__ Wv2)
{
    const int idx = blockIdx.x * 256 + threadIdx.x;
    if (idx >= QKVP * HH) return;
    const int r = idx >> 7, c = idx & 127;
    float v = 0.f;
    if (r < QKVW) {
        const int sel = r / 96, rr = r - sel * 96;
        const float* W = sel == 0 ? Wq1 : sel == 1 ? Wk1 : sel == 2 ? Wv1
                       : sel == 3 ? Wq2 : sel == 4 ? Wk2 : Wv2;
        v = W[rr * HH + c];
    }
    w_qkv[idx] = __float2half_rn(v);
}

__global__ void pack_qkv_b_kernel(const float* __restrict__ bq1, const float* __restrict__ bk1,
                                  const float* __restrict__ bv1, const float* __restrict__ bq2,
                                  const float* __restrict__ bk2, const float* __restrict__ bv2)
{
    const int i = blockIdx.x * 256 + threadIdx.x;
    if (i >= QKVP) return;
    float v = 0.f;
    if (i < QKVW) {
        const int sel = i / 96, rr = i - sel * 96;
        const float* b = sel == 0 ? bq1 : sel == 1 ? bk1 : sel == 2 ? bv1
                       : sel == 3 ? bq2 : sel == 4 ? bk2 : bv2;
        v = b[rr];
    }
    b_qkvp[i] = v;
}

__global__ void pack_fin_kernel(const float* __restrict__ W, const float* __restrict__ b)
{
    const int idx = blockIdx.x * 256 + threadIdx.x;
    if (idx < OUTP * HH) {
        const int r = idx >> 7;
        w_fin[idx] = __float2half_rn((r < OUTV) ? W[idx] : 0.f);
    }
    if (idx < OUTP) b_finp[idx] = (idx < OUTV) ? b[idx] : 0.f;
}

// ---------------------------------------------------------------------------
// Launch
// ---------------------------------------------------------------------------
extern "C" void kernel_launch(void* const* d_in, const int* in_sizes, int n_in,
                              void* d_out, int out_size)
{
    const int*   inp   = (const int*)  d_in[0];
    const float* emb   = (const float*)d_in[1];
    const float* pos   = (const float*)d_in[2];
    const float* Wk1   = (const float*)d_in[3];
    const float* bk1   = (const float*)d_in[4];
    const float* Wv1   = (const float*)d_in[5];
    const float* bv1   = (const float*)d_in[6];
    const float* Wq1   = (const float*)d_in[7];
    const float* bq1   = (const float*)d_in[8];
    const float* Wk2   = (const float*)d_in[9];
    const float* bk2   = (const float*)d_in[10];
    const float* Wv2   = (const float*)d_in[11];
    const float* bv2   = (const float*)d_in[12];
    const float* Wq2   = (const float*)d_in[13];
    const float* bq2   = (const float*)d_in[14];
    const float* Wproj = (const float*)d_in[15];
    const float* bproj = (const float*)d_in[16];
    const float* gmh   = (const float*)d_in[17];
    const float* bmh   = (const float*)d_in[18];
    const float* Wff1  = (const float*)d_in[19];
    const float* bff1  = (const float*)d_in[20];
    const float* Wff2  = (const float*)d_in[21];
    const float* bff2  = (const float*)d_in[22];
    const float* gff   = (const float*)d_in[23];
    const float* bff   = (const float*)d_in[24];
    const float* Wfin  = (const float*)d_in[25];
    const float* bfin  = (const float*)d_in[26];
    float* out = (float*)d_out;

    float  *pX0, *pQkv, *pMh, *pX1, *pFFo;
    __half *pX0h, *pHeads, *pX1h, *pFF, *pX2h;
    __half *pWqkv, *pWproj, *pWff1, *pWff2, *pWfin;
    float  *pBqkv, *pBfin;
    cudaGetSymbolAddress((void**)&pX0,    d_x0);
    cudaGetSymbolAddress((void**)&pX0h,   d_x0h);
    cudaGetSymbolAddress((void**)&pQkv,   d_qkvb);
    cudaGetSymbolAddress((void**)&pHeads, d_heads);
    cudaGetSymbolAddress((void**)&pMh,    d_mhb);
    cudaGetSymbolAddress((void**)&pX1,    d_x1);
    cudaGetSymbolAddress((void**)&pX1h,   d_x1h);
    cudaGetSymbolAddress((void**)&pFF,    d_ff);
    cudaGetSymbolAddress((void**)&pFFo,   d_ffo);
    cudaGetSymbolAddress((void**)&pX2h,   d_x2h);
    cudaGetSymbolAddress((void**)&pWqkv,  w_qkv);
    cudaGetSymbolAddress((void**)&pBqkv,  b_qkvp);
    cudaGetSymbolAddress((void**)&pWproj, w_proj);
    cudaGetSymbolAddress((void**)&pWff1,  w_ff1);
    cudaGetSymbolAddress((void**)&pWff2,  w_ff2);
    cudaGetSymbolAddress((void**)&pWfin,  w_fin);
    cudaGetSymbolAddress((void**)&pBfin,  b_finp);

    const int SMBIG = 3 * (128 + 256) * 72 * 2;        // 165888 bytes
    const int SMSML = 3 * (128 + 128) * 72 * 2;        // 110592 bytes
    const int SMATT = (3 * 43 * 97 + 43 * 44) * 4;     // 57620 bytes
    cudaFuncSetAttribute(gemm_ldsm<256, float, false>,
                         cudaFuncAttributeMaxDynamicSharedMemorySize, SMBIG);
    cudaFuncSetAttribute(gemm_ldsm<256, __half, true>,
                         cudaFuncAttributeMaxDynamicSharedMemorySize, SMBIG);
    cudaFuncSetAttribute(gemm_ldsm<128, float, false>,
                         cudaFuncAttributeMaxDynamicSharedMemorySize, SMSML);
    cudaFuncSetAttribute(attn_kernel,
                         cudaFuncAttributeMaxDynamicSharedMemorySize, SMATT);

    // --- weight prep ---
    pack_qkv_w_kernel<<<(QKVP * HH + 255) / 256, 256>>>(Wq1, Wk1, Wv1, Wq2, Wk2, Wv2);
    pack_qkv_b_kernel<<<3, 256>>>(bq1, bk1, bv1, bq2, bk2, bv2);
    round_all_kernel<<<(HH * 192 + DFF_ * HH + HH * DFF_ + 255) / 256, 256>>>(Wproj, Wff1, Wff2);
    pack_fin_kernel<<<(OUTP * HH + 255) / 256, 256>>>(Wfin, bfin);

    // --- forward ---
    embed_kernel<<<(M_TOK * HH) / 256, 256>>>(inp, emb, pos);

    // QKV: [M,128] @ [576(pad768),128]^T -> fp32
    gemm_ldsm<256, float, false><<<dim3(172, 3), 256, SMBIG>>>(
        pX0h, pWqkv, pBqkv, pQkv, 128, QKVW, QKVW);

    attn_kernel<<<dim3(NB, 2), 256, SMATT>>>(pQkv, pHeads);

    // proj: [M,192] @ [128,192]^T -> fp32
    gemm_ldsm<128, float, false><<<dim3(172, 1), 256, SMSML>>>(
        pHeads, pWproj, bproj, pMh, 192, HH, HH);

    add_ln_kernel<<<M_TOK / 8, 256>>>(pMh, pX0, gmh, bmh, pX1, pX1h);

    // FF1 + relu -> fp16: [M,128] @ [2048,128]^T
    gemm_ldsm<256, __half, true><<<dim3(172, 8), 256, SMBIG>>>(
        pX1h, pWff1, bff1, pFF, 128, DFF_, DFF_);

    // FF2: [M,2048] @ [128,2048]^T -> fp32
    gemm_ldsm<128, float, false><<<dim3(172, 1), 256, SMSML>>>(
        pFF, pWff2, bff2, pFFo, DFF_, HH, HH);

    add_ln_kernel<<<M_TOK / 8, 256>>>(pFFo, pX1, gff, bff, nullptr, pX2h);

    // Final: [M,128] @ [8000(pad8192),128]^T -> d_out (fp32)
    gemm_ldsm<256, float, false><<<dim3(172, 32), 256, SMBIG>>>(
        pX2h, pWfin, pBfin, out, 128, OUTV, OUTV);
}

// round 16
// speedup vs baseline: 1.7847x; 1.1964x over previous
#include <cuda_runtime.h>
#include <cuda_fp16.h>
#include <math.h>
#include <cstdint>

// ---------------------------------------------------------------------------
// Problem constants
// ---------------------------------------------------------------------------
#define M_TOK 22016   // N*T = 512*43
#define NB    512
#define TT    43
#define HH    128
#define DKH   96
#define DFF_  2048
#define OUTV  8000
#define OUTP  8064    // padded to multiple of 128
#define QKVW  576     // 6*96 packed
#define QKVP  640     // padded to multiple of 128

// ---------------------------------------------------------------------------
// Device-global scratch (no allocation allowed)
// ---------------------------------------------------------------------------
__device__ float  d_x0  [M_TOK * HH];      // embed, exact fp32
__device__ __half d_x0h [M_TOK * HH];      // embed, fp16
__device__ float  d_qkvb[M_TOK * QKVW];    // packed q1 k1 v1 q2 k2 v2 (fp32)
__device__ __half d_heads[M_TOK * 192];    // concat(h1,h2), fp16
__device__ float  d_mhb [M_TOK * HH];      // proj output
__device__ float  d_x1  [M_TOK * HH];      // LN1 out exact
__device__ __half d_x1h [M_TOK * HH];      // LN1 out fp16
__device__ __half d_ff  [M_TOK * DFF_];    // relu(ff1), fp16
__device__ float  d_ffo [M_TOK * HH];      // ff2 output
__device__ __half d_x2h [M_TOK * HH];      // LN2 out fp16

__device__ __half w_qkv [QKVP * HH];       // packed+padded fp16
__device__ float  b_qkvp[QKVP];
__device__ __half w_proj[HH * 192];
__device__ __half w_ff1 [DFF_ * HH];
__device__ __half w_ff2 [HH * DFF_];
__device__ __half w_fin [OUTP * HH];       // padded rows zeroed
__device__ float  b_finp[OUTP];

// ---------------------------------------------------------------------------
// Helpers
// ---------------------------------------------------------------------------
__device__ __forceinline__ unsigned int smem_u32(const void* p) {
    return (unsigned int)__cvta_generic_to_shared(p);
}
__device__ __forceinline__ void cp16(unsigned int dst, const void* src) {
    asm volatile("cp.async.cg.shared.global [%0], [%1], 16;\n" :: "r"(dst), "l"(src));
}
__device__ __forceinline__ void mma_f16(float (&d)[4], const unsigned int (&a)[4],
                                        const unsigned int (&b)[2]) {
    asm volatile(
        "mma.sync.aligned.m16n8k16.row.col.f32.f16.f16.f32 "
        "{%0,%1,%2,%3},{%4,%5,%6,%7},{%8,%9},{%0,%1,%2,%3};"
        : "+f"(d[0]), "+f"(d[1]), "+f"(d[2]), "+f"(d[3])
        : "r"(a[0]), "r"(a[1]), "r"(a[2]), "r"(a[3]), "r"(b[0]), "r"(b[1]));
}
__device__ __forceinline__ void ldsm4(unsigned int& r0, unsigned int& r1,
                                      unsigned int& r2, unsigned int& r3,
                                      unsigned int addr) {
    asm volatile("ldmatrix.sync.aligned.m8n8.x4.shared.b16 {%0,%1,%2,%3}, [%4];"
                 : "=r"(r0), "=r"(r1), "=r"(r2), "=r"(r3) : "r"(addr));
}

// ---------------------------------------------------------------------------
// Single-stage K=128 GEMM: C[M,N] = A[M,128] @ B[N,128]^T + bias.
// Whole K resident in smem (A 128x128 + B 128x128 halves, pitch 136 =>
// conflict-free ldmatrix). No pipeline; 2 CTAs/SM so one CTA's loads overlap
// the other's MMAs. 256 threads = 8 warps (2M x 4N), warp tile 64x32.
// B rows must cover n0..n0+127 (weights padded); stores masked col < Nstore.
// ---------------------------------------------------------------------------
template <typename OutT, bool RELU>
__global__ void __launch_bounds__(256, 2)
gemm_k128(const __half* __restrict__ A, const __half* __restrict__ B,
          const float* __restrict__ bias, OutT* __restrict__ C,
          int ldc, int Nstore)
{
    constexpr int LDH = 136;                 // halves per smem row (128 + 8 pad)
    extern __shared__ __half smh[];

    const int tid  = threadIdx.x;
    const int wid  = tid >> 5;
    const int lane = tid & 31;
    const int wr   = wid >> 2;               // 0..1
    const int wc   = wid & 3;                // 0..3
    const int g    = lane >> 2;              // 0..7
    const int tg   = lane & 3;               // 0..3

    const __half* Ab = A + (size_t)blockIdx.x * 128 * 128;
    const __half* Bb = B + (size_t)blockIdx.y * 128 * 128;
    const unsigned int sb = smem_u32(smh);

    // Load entire A and B tiles: 2048 + 2048 16B units, 16 per thread.
#pragma unroll
    for (int i = 0; i < 8; i++) {
        int t = tid + 256 * i;
        int row = t >> 4, c = t & 15;
        cp16(sb + (unsigned)(row * LDH + c * 8) * 2, Ab + row * 128 + c * 8);
    }
#pragma unroll
    for (int i = 0; i < 8; i++) {
        int t = tid + 256 * i;
        int row = t >> 4, c = t & 15;
        cp16(sb + (unsigned)((128 + row) * LDH + c * 8) * 2, Bb + row * 128 + c * 8);
    }
    asm volatile("cp.async.commit_group;" ::);

    float acc[4][4][4];
#pragma unroll
    for (int i = 0; i < 4; i++)
#pragma unroll
        for (int j = 0; j < 4; j++)
#pragma unroll
            for (int q = 0; q < 4; q++) acc[i][j][q] = 0.f;

    const int mrow = (lane & 7) + ((lane >> 3) & 1) * 8;
    const int mcol = (lane >> 4) * 8;
    const unsigned int a_off = sb + (unsigned)((wr * 64 + mrow) * LDH + mcol) * 2;
    const unsigned int b_off = sb + (unsigned)((128 + wc * 32 + mrow) * LDH + mcol) * 2;

    asm volatile("cp.async.wait_group 0;" ::);
    __syncthreads();

#pragma unroll
    for (int ks = 0; ks < 8; ++ks) {
        const unsigned int kb = (unsigned)(ks * 16) * 2;
        unsigned int a[4][4], b[4][2];
#pragma unroll
        for (int mf = 0; mf < 4; ++mf)
            ldsm4(a[mf][0], a[mf][1], a[mf][2], a[mf][3],
                  a_off + (unsigned)(mf * 16 * LDH) * 2 + kb);
#pragma unroll
        for (int p = 0; p < 2; ++p)
            ldsm4(b[2 * p][0], b[2 * p + 1][0], b[2 * p][1], b[2 * p + 1][1],
                  b_off + (unsigned)(p * 16 * LDH) * 2 + kb);
#pragma unroll
        for (int mf = 0; mf < 4; ++mf)
#pragma unroll
            for (int nf = 0; nf < 4; ++nf)
                mma_f16(acc[mf][nf], a[mf], b[nf]);
    }

    const int n0 = blockIdx.y * 128;
#pragma unroll
    for (int mf = 0; mf < 4; ++mf) {
#pragma unroll
        for (int nf = 0; nf < 4; ++nf) {
            const int c = n0 + wc * 32 + nf * 8 + tg * 2;
            if (c < Nstore) {
                const float bi0 = bias[c];
                const float bi1 = bias[c + 1];
#pragma unroll
                for (int h = 0; h < 2; ++h) {
                    const int r = blockIdx.x * 128 + wr * 64 + mf * 16 + g + h * 8;
                    float v0 = acc[mf][nf][h * 2 + 0] + bi0;
                    float v1 = acc[mf][nf][h * 2 + 1] + bi1;
                    if (RELU) { v0 = fmaxf(v0, 0.f); v1 = fmaxf(v1, 0.f); }
                    OutT* dst = C + (size_t)r * ldc + c;
                    if (sizeof(OutT) == 4) {
                        float2 val; val.x = v0; val.y = v1;
                        *reinterpret_cast<float2*>(dst) = val;
                    } else {
                        __half2 hv = __floats2half2_rn(v0, v1);
                        *reinterpret_cast<__half2*>(dst) = hv;
                    }
                }
            }
        }
    }
}

// ---------------------------------------------------------------------------
// Pipelined GEMM for K > 128 (proj K=192, FF2 K=2048). NT=128, BK=64,
// 2-stage cp.async, ldmatrix fragments, 2 CTAs/SM. K % 64 == 0.
// ---------------------------------------------------------------------------
template <typename OutT, bool RELU>
__global__ void __launch_bounds__(256, 2)
gemm_pipe(const __half* __restrict__ A, const __half* __restrict__ B,
          const float* __restrict__ bias, OutT* __restrict__ C,
          int K, int ldc, int Nstore)
{
    constexpr int LDH = 72;
    constexpr int STG = 256 * LDH;           // halves per stage (A128 + B128 rows)
    extern __shared__ __half smh[];

    const int tid  = threadIdx.x;
    const int wid  = tid >> 5;
    const int lane = tid & 31;
    const int wr   = wid >> 2;
    const int wc   = wid & 3;
    const int g    = lane >> 2;
    const int tg   = lane & 3;

    const int KT = K >> 6;
    const __half* Ab = A + (size_t)blockIdx.x * 128 * K;
    const __half* Bb = B + (size_t)blockIdx.y * 128 * K;
    const unsigned int sb = smem_u32(smh);

    float acc[4][4][4];
#pragma unroll
    for (int i = 0; i < 4; i++)
#pragma unroll
        for (int j = 0; j < 4; j++)
#pragma unroll
            for (int q = 0; q < 4; q++) acc[i][j][q] = 0.f;

    auto load_stage = [&](int buf, int kt) {
        const unsigned int ab = sb + (unsigned)buf * STG * 2;
        const unsigned int bb = ab + 128 * LDH * 2;
        const int kof = kt * 64;
#pragma unroll
        for (int i = 0; i < 4; i++) {
            int t = tid + 256 * i;
            int row = t >> 3, c = t & 7;
            cp16(ab + (unsigned)(row * LDH + c * 8) * 2,
                 Ab + (size_t)row * K + kof + c * 8);
        }
#pragma unroll
        for (int i = 0; i < 4; i++) {
            int t = tid + 256 * i;
            int row = t >> 3, c = t & 7;
            cp16(bb + (unsigned)(row * LDH + c * 8) * 2,
                 Bb + (size_t)row * K + kof + c * 8);
        }
        asm volatile("cp.async.commit_group;" ::);
    };

    const int mrow = (lane & 7) + ((lane >> 3) & 1) * 8;
    const int mcol = (lane >> 4) * 8;
    const unsigned int a_off = (unsigned)((wr * 64 + mrow) * LDH + mcol) * 2;
    const unsigned int b_off = (unsigned)(128 * LDH + (wc * 32 + mrow) * LDH + mcol) * 2;

    load_stage(0, 0);
    for (int kc = 0; kc < KT; ++kc) {
        const int buf = kc & 1;
        asm volatile("cp.async.wait_group 0;" ::);
        __syncthreads();
        if (kc + 1 < KT) load_stage(buf ^ 1, kc + 1);

        const unsigned int stg = sb + (unsigned)(buf * STG) * 2;
#pragma unroll
        for (int ks = 0; ks < 4; ++ks) {
            const unsigned int kb = (unsigned)(ks * 16) * 2;
            unsigned int a[4][4], b[4][2];
#pragma unroll
            for (int mf = 0; mf < 4; ++mf)
                ldsm4(a[mf][0], a[mf][1], a[mf][2], a[mf][3],
                      stg + a_off + (unsigned)(mf * 16 * LDH) * 2 + kb);
#pragma unroll
            for (int p = 0; p < 2; ++p)
                ldsm4(b[2 * p][0], b[2 * p + 1][0], b[2 * p][1], b[2 * p + 1][1],
                      stg + b_off + (unsigned)(p * 16 * LDH) * 2 + kb);
#pragma unroll
            for (int mf = 0; mf < 4; ++mf)
#pragma unroll
                for (int nf = 0; nf < 4; ++nf)
                    mma_f16(acc[mf][nf], a[mf], b[nf]);
        }
        __syncthreads();
    }

    const int n0 = blockIdx.y * 128;
#pragma unroll
    for (int mf = 0; mf < 4; ++mf) {
#pragma unroll
        for (int nf = 0; nf < 4; ++nf) {
            const int c = n0 + wc * 32 + nf * 8 + tg * 2;
            if (c < Nstore) {
                const float bi0 = bias[c];
                const float bi1 = bias[c + 1];
#pragma unroll
                for (int h = 0; h < 2; ++h) {
                    const int r = blockIdx.x * 128 + wr * 64 + mf * 16 + g + h * 8;
                    float v0 = acc[mf][nf][h * 2 + 0] + bi0;
                    float v1 = acc[mf][nf][h * 2 + 1] + bi1;
                    if (RELU) { v0 = fmaxf(v0, 0.f); v1 = fmaxf(v1, 0.f); }
                    OutT* dst = C + (size_t)r * ldc + c;
                    if (sizeof(OutT) == 4) {
                        float2 val; val.x = v0; val.y = v1;
                        *reinterpret_cast<float2*>(dst) = val;
                    } else {
                        __half2 hv = __floats2half2_rn(v0, v1);
                        *reinterpret_cast<__half2*>(dst) = hv;
                    }
                }
            }
        }
    }
}

// ---------------------------------------------------------------------------
// Attention: one CTA per (batch, head). All fp32 in smem; fp16 output.
// ---------------------------------------------------------------------------
__global__ void __launch_bounds__(256, 1)
attn_kernel(const float* __restrict__ qkv, __half* __restrict__ heads)
{
    extern __shared__ float sm[];
    float* q  = sm;                 // 43*97
    float* k  = q + 43 * 97;
    float* v  = k + 43 * 97;
    float* sc = v + 43 * 97;        // 43*44

    const int n = blockIdx.x, head = blockIdx.y;
    const int tid = threadIdx.x;
    const float* base = qkv + (size_t)(n * TT) * QKVW + head * 288;

    for (int idx = tid; idx < TT * DKH; idx += 256) {
        int i = idx / DKH, d = idx - i * DKH;
        const float* row = base + (size_t)i * QKVW;
        q[i * 97 + d] = row[d];
        k[i * 97 + d] = row[96 + d];
        v[i * 97 + d] = row[192 + d];
    }
    __syncthreads();

    const float scale = 0.10206207261596577f;   // 1/sqrt(96)
    for (int p = tid; p < TT * TT; p += 256) {
        int i = p / TT, j = p - i * TT;
        float s = 0.f;
#pragma unroll 16
        for (int d = 0; d < DKH; ++d) s += q[i * 97 + d] * k[j * 97 + d];
        sc[i * 44 + j] = s * scale;
    }
    __syncthreads();

    const int warpId = tid >> 5, lane = tid & 31;
    for (int i = warpId; i < TT; i += 8) {
        float x0 = (lane < TT)      ? sc[i * 44 + lane]      : -1e30f;
        float x1 = (lane + 32 < TT) ? sc[i * 44 + lane + 32] : -1e30f;
        float m = fmaxf(x0, x1);
#pragma unroll
        for (int o = 16; o; o >>= 1) m = fmaxf(m, __shfl_xor_sync(0xffffffffu, m, o));
        float e0 = (lane < TT)      ? expf(x0 - m) : 0.f;
        float e1 = (lane + 32 < TT) ? expf(x1 - m) : 0.f;
        float s = e0 + e1;
#pragma unroll
        for (int o = 16; o; o >>= 1) s += __shfl_xor_sync(0xffffffffu, s, o);
        float inv = 1.f / s;
        if (lane < TT)      sc[i * 44 + lane]      = e0 * inv;
        if (lane + 32 < TT) sc[i * 44 + lane + 32] = e1 * inv;
    }
    __syncthreads();

    __half* out = heads + (size_t)(n * TT) * 192 + head * 96;
    for (int idx = tid; idx < TT * DKH; idx += 256) {
        int i = idx / DKH, d = idx - i * DKH;
        float o = 0.f;
#pragma unroll
        for (int j = 0; j < TT; ++j) o += sc[i * 44 + j] * v[j * 97 + d];
        out[(size_t)i * 192 + d] = __float2half_rn(o);
    }
}

// ---------------------------------------------------------------------------
// Fused add + LayerNorm. One warp per token; exact fp32 + fp16 outputs.
// ---------------------------------------------------------------------------
__global__ void __launch_bounds__(256, 1)
add_ln_kernel(const float* __restrict__ a, const float* __restrict__ res,
              const float* __restrict__ gam, const float* __restrict__ bet,
              float* __restrict__ outE, __half* __restrict__ outH)
{
    const int warpId = threadIdx.x >> 5, lane = threadIdx.x & 31;
    const int m = blockIdx.x * 8 + warpId;
    const float* ap = a   + (size_t)m * HH;
    const float* rp = res + (size_t)m * HH;
    float x[4];
    float s = 0.f, ss = 0.f;
#pragma unroll
    for (int q = 0; q < 4; q++) {
        x[q] = ap[lane + 32 * q] + rp[lane + 32 * q];
        s += x[q]; ss += x[q] * x[q];
    }
#pragma unroll
    for (int o = 16; o; o >>= 1) {
        s  += __shfl_xor_sync(0xffffffffu, s,  o);
        ss += __shfl_xor_sync(0xffffffffu, ss, o);
    }
    const float mean = s * (1.f / 128.f);
    const float var  = ss * (1.f / 128.f) - mean * mean;
    const float rstd = rsqrtf(var + 1e-5f);
#pragma unroll
    for (int q = 0; q < 4; q++) {
        const int h = lane + 32 * q;
        const float y = (x[q] - mean) * rstd * gam[h] + bet[h];
        if (outE) outE[(size_t)m * HH + h] = y;
        outH[(size_t)m * HH + h] = __float2half_rn(y);
    }
}

// ---------------------------------------------------------------------------
// Embedding: word + positional, exact fp32 + fp16 copies.
// ---------------------------------------------------------------------------
__global__ void embed_kernel(const int* __restrict__ inp,
                             const float* __restrict__ emb,
                             const float* __restrict__ pos)
{
    const int idx = blockIdx.x * 256 + threadIdx.x;     // < M_TOK*128
    const int m = idx >> 7, h = idx & 127;
    const int t = m % TT;
    const int id = inp[m];
    const float v = emb[(size_t)id * HH + h] + pos[t * HH + h];
    d_x0[idx]  = v;
    d_x0h[idx] = __float2half_rn(v);
}

// ---------------------------------------------------------------------------
// Weight prep kernels (run every call; cheap, graph-capturable)
// ---------------------------------------------------------------------------
__global__ void round_all_kernel(const float* __restrict__ Wp,
                                 const float* __restrict__ W1,
                                 const float* __restrict__ W2)
{
    const int i = blockIdx.x * 256 + threadIdx.x;
    const int n1 = HH * 192, n2 = DFF_ * HH, n3 = HH * DFF_;
    if (i < n1)                w_proj[i]          = __float2half_rn(Wp[i]);
    else if (i < n1 + n2)      w_ff1[i - n1]      = __float2half_rn(W1[i - n1]);
    else if (i < n1 + n2 + n3) w_ff2[i - n1 - n2] = __float2half_rn(W2[i - n1 - n2]);
}

__global__ void pack_qkv_w_kernel(const float* __restrict__ Wq1, const float* __restrict__ Wk1,
                                  const float* __restrict__ Wv1, const float* __restrict__ Wq2,
                                  const float* __restrict__ Wk2, const float* __restrict__ Wv2)
{
    const int idx = blockIdx.x * 256 + threadIdx.x;
    if (idx >= QKVP * HH) return;
    const int r = idx >> 7, c = idx & 127;
    float v = 0.f;
    if (r < QKVW) {
        const int sel = r / 96, rr = r - sel * 96;
        const float* W = sel == 0 ? Wq1 : sel == 1 ? Wk1 : sel == 2 ? Wv1
                       : sel == 3 ? Wq2 : sel == 4 ? Wk2 : Wv2;
        v = W[rr * HH + c];
    }
    w_qkv[idx] = __float2half_rn(v);
}

__global__ void pack_qkv_b_kernel(const float* __restrict__ bq1, const float* __restrict__ bk1,
                                  const float* __restrict__ bv1, const float* __restrict__ bq2,
                                  const float* __restrict__ bk2, const float* __restrict__ bv2)
{
    const int i = blockIdx.x * 256 + threadIdx.x;
    if (i >= QKVP) return;
    float v = 0.f;
    if (i < QKVW) {
        const int sel = i / 96, rr = i - sel * 96;
        const float* b = sel == 0 ? bq1 : sel == 1 ? bk1 : sel == 2 ? bv1
                       : sel == 3 ? bq2 : sel == 4 ? bk2 : bv2;
        v = b[rr];
    }
    b_qkvp[i] = v;
}

__global__ void pack_fin_kernel(const float* __restrict__ W, const float* __restrict__ b)
{
    const int idx = blockIdx.x * 256 + threadIdx.x;
    if (idx < OUTP * HH) {
        const int r = idx >> 7;
        w_fin[idx] = __float2half_rn((r < OUTV) ? W[idx] : 0.f);
    }
    if (idx < OUTP) b_finp[idx] = (idx < OUTV) ? b[idx] : 0.f;
}

// ---------------------------------------------------------------------------
// Launch
// ---------------------------------------------------------------------------
extern "C" void kernel_launch(void* const* d_in, const int* in_sizes, int n_in,
                              void* d_out, int out_size)
{
    const int*   inp   = (const int*)  d_in[0];
    const float* emb   = (const float*)d_in[1];
    const float* pos   = (const float*)d_in[2];
    const float* Wk1   = (const float*)d_in[3];
    const float* bk1   = (const float*)d_in[4];
    const float* Wv1   = (const float*)d_in[5];
    const float* bv1   = (const float*)d_in[6];
    const float* Wq1   = (const float*)d_in[7];
    const float* bq1   = (const float*)d_in[8];
    const float* Wk2   = (const float*)d_in[9];
    const float* bk2   = (const float*)d_in[10];
    const float* Wv2   = (const float*)d_in[11];
    const float* bv2   = (const float*)d_in[12];
    const float* Wq2   = (const float*)d_in[13];
    const float* bq2   = (const float*)d_in[14];
    const float* Wproj = (const float*)d_in[15];
    const float* bproj = (const float*)d_in[16];
    const float* gmh   = (const float*)d_in[17];
    const float* bmh   = (const float*)d_in[18];
    const float* Wff1  = (const float*)d_in[19];
    const float* bff1  = (const float*)d_in[20];
    const float* Wff2  = (const float*)d_in[21];
    const float* bff2  = (const float*)d_in[22];
    const float* gff   = (const float*)d_in[23];
    const float* bff   = (const float*)d_in[24];
    const float* Wfin  = (const float*)d_in[25];
    const float* bfin  = (const float*)d_in[26];
    float* out = (float*)d_out;

    float  *pX0, *pQkv, *pMh, *pX1, *pFFo;
    __half *pX0h, *pHeads, *pX1h, *pFF, *pX2h;
    __half *pWqkv, *pWproj, *pWff1, *pWff2, *pWfin;
    float  *pBqkv, *pBfin;
    cudaGetSymbolAddress((void**)&pX0,    d_x0);
    cudaGetSymbolAddress((void**)&pX0h,   d_x0h);
    cudaGetSymbolAddress((void**)&pQkv,   d_qkvb);
    cudaGetSymbolAddress((void**)&pHeads, d_heads);
    cudaGetSymbolAddress((void**)&pMh,    d_mhb);
    cudaGetSymbolAddress((void**)&pX1,    d_x1);
    cudaGetSymbolAddress((void**)&pX1h,   d_x1h);
    cudaGetSymbolAddress((void**)&pFF,    d_ff);
    cudaGetSymbolAddress((void**)&pFFo,   d_ffo);
    cudaGetSymbolAddress((void**)&pX2h,   d_x2h);
    cudaGetSymbolAddress((void**)&pWqkv,  w_qkv);
    cudaGetSymbolAddress((void**)&pBqkv,  b_qkvp);
    cudaGetSymbolAddress((void**)&pWproj, w_proj);
    cudaGetSymbolAddress((void**)&pWff1,  w_ff1);
    cudaGetSymbolAddress((void**)&pWff2,  w_ff2);
    cudaGetSymbolAddress((void**)&pWfin,  w_fin);
    cudaGetSymbolAddress((void**)&pBfin,  b_finp);

    const int SMK128 = 256 * 136 * 2;                  // 69632 bytes
    const int SMPIPE = 2 * 256 * 72 * 2;               // 73728 bytes
    const int SMATT  = (3 * 43 * 97 + 43 * 44) * 4;    // 57620 bytes
    cudaFuncSetAttribute(gemm_k128<float, false>,
                         cudaFuncAttributeMaxDynamicSharedMemorySize, SMK128);
    cudaFuncSetAttribute(gemm_k128<__half, true>,
                         cudaFuncAttributeMaxDynamicSharedMemorySize, SMK128);
    cudaFuncSetAttribute(gemm_pipe<float, false>,
                         cudaFuncAttributeMaxDynamicSharedMemorySize, SMPIPE);
    cudaFuncSetAttribute(attn_kernel,
                         cudaFuncAttributeMaxDynamicSharedMemorySize, SMATT);

    // --- weight prep ---
    pack_qkv_w_kernel<<<(QKVP * HH + 255) / 256, 256>>>(Wq1, Wk1, Wv1, Wq2, Wk2, Wv2);
    pack_qkv_b_kernel<<<3, 256>>>(bq1, bk1, bv1, bq2, bk2, bv2);
    round_all_kernel<<<(HH * 192 + DFF_ * HH + HH * DFF_ + 255) / 256, 256>>>(Wproj, Wff1, Wff2);
    pack_fin_kernel<<<(OUTP * HH + 255) / 256, 256>>>(Wfin, bfin);

    // --- forward ---
    embed_kernel<<<(M_TOK * HH) / 256, 256>>>(inp, emb, pos);

    // QKV: [M,128] @ [576(pad640),128]^T -> fp32
    gemm_k128<float, false><<<dim3(172, 5), 256, SMK128>>>(
        pX0h, pWqkv, pBqkv, pQkv, QKVW, QKVW);

    attn_kernel<<<dim3(NB, 2), 256, SMATT>>>(pQkv, pHeads);

    // proj: [M,192] @ [128,192]^T -> fp32
    gemm_pipe<float, false><<<dim3(172, 1), 256, SMPIPE>>>(
        pHeads, pWproj, bproj, pMh, 192, HH, HH);

    add_ln_kernel<<<M_TOK / 8, 256>>>(pMh, pX0, gmh, bmh, pX1, pX1h);

    // FF1 + relu -> fp16: [M,128] @ [2048,128]^T
    gemm_k128<__half, true><<<dim3(172, 16), 256, SMK128>>>(
        pX1h, pWff1, bff1, pFF, DFF_, DFF_);

    // FF2: [M,2048] @ [128,2048]^T -> fp32
    gemm_pipe<float, false><<<dim3(172, 1), 256, SMPIPE>>>(
        pFF, pWff2, bff2, pFFo, DFF_, HH, HH);

    add_ln_kernel<<<M_TOK / 8, 256>>>(pFFo, pX1, gff, bff, nullptr, pX2h);

    // Final: [M,128] @ [8000(pad8064),128]^T -> d_out (fp32)
    gemm_k128<float, false><<<dim3(172, 63), 256, SMK128>>>(
        pX2h, pWfin, pBfin, out, QKVW /*unused*/ == 0 ? OUTV : OUTV, OUTV);
}